// round 17
// baseline (speedup 1.0000x reference)
#include <cuda_runtime.h>
#include <cuda_fp16.h>
#include <stdint.h>

// rgb[n,d] = (1/Z_n) * sum_e enc[n,e] * D[n, d*72+e]
// D = A @ W',  A[n,c] = exp2(s'_nc - ub_n),  s' = x[:3].(centroid*log2e),
// ub_n = |x[:3]| * max_c |centroid'_c|
// WARP-SPECIALIZED, 24 warps: warps 16-23 produce (softmax/enc/pack t+1, out t-1),
// warps 0-15 consume (HMMA GEMM tile t; 2 m-halves x 8 k-eighths, full n).
// R17 = R16 with racc init fixed (all 1024 entries zeroed; R16 left 768..1023
// stale across graph replays -> post-timing divergence).

constexpr int TPB    = 768;
constexpr int TILE_M = 128;
constexpr int NC     = 256;
constexpr int EDIM   = 72;
constexpr int NOUT   = 216;

constexpr int ROW_B  = 528;            // A/W' smem row bytes (132 words)
constexpr int ENC_B  = 544;            // bytes per enc e-pair row (136 words)
constexpr int ENC_BUF = 36 * ENC_B;    // 19584

constexpr int OFF_CENT = 0;                          // 4096
constexpr int OFF_ZBUF = 4160;                       // 1024 (also warp-max scratch)
constexpr int OFF_WP   = 5184;                       // 216*528 = 114048
constexpr int OFF_A    = OFF_WP + NOUT * ROW_B;      // 119232 (single A tile)
constexpr int OFF_ENC  = OFF_A + TILE_M * ROW_B;     // 186816 (x2 buffers)
constexpr int OFF_INVZ = OFF_ENC + 2 * ENC_BUF;      // 225984 (2*128 floats)
constexpr int OFF_RACC = OFF_INVZ + 1024;            // 227008 (2*512 floats)
constexpr int SMEM_BYTES = OFF_RACC + 4096;          // 231104

constexpr float LOG2E = 1.4426950408889634f;

__device__ __forceinline__ uint32_t s2u(const void* p) {
    uint32_t a;
    asm("{ .reg .u64 t; cvta.to.shared.u64 t, %1; cvt.u32.u64 %0, t; }"
        : "=r"(a) : "l"(p));
    return a;
}
__device__ __forceinline__ void ldsm4(uint32_t* r, uint32_t addr) {
    asm volatile("ldmatrix.sync.aligned.m8n8.x4.shared.b16 {%0,%1,%2,%3}, [%4];"
                 : "=r"(r[0]), "=r"(r[1]), "=r"(r[2]), "=r"(r[3]) : "r"(addr));
}
__device__ __forceinline__ void ldsm2(uint32_t* r, uint32_t addr) {
    asm volatile("ldmatrix.sync.aligned.m8n8.x2.shared.b16 {%0,%1}, [%2];"
                 : "=r"(r[0]), "=r"(r[1]) : "r"(addr));
}
__device__ __forceinline__ void lds128(uint32_t& r0, uint32_t& r1,
                                       uint32_t& r2, uint32_t& r3, uint32_t addr) {
    asm volatile("ld.shared.v4.b32 {%0,%1,%2,%3}, [%4];"
                 : "=r"(r0), "=r"(r1), "=r"(r2), "=r"(r3) : "r"(addr));
}
__device__ __forceinline__ void hmma(float& d0, float& d1, float& d2, float& d3,
                                     const uint32_t* a, const uint32_t* b) {
    asm volatile("mma.sync.aligned.m16n8k16.row.col.f32.f16.f16.f32 "
                 "{%0,%1,%2,%3}, {%4,%5,%6,%7}, {%8,%9}, {%0,%1,%2,%3};"
                 : "+f"(d0), "+f"(d1), "+f"(d2), "+f"(d3)
                 : "r"(a[0]), "r"(a[1]), "r"(a[2]), "r"(a[3]), "r"(b[0]), "r"(b[1]));
}
// First-kstep HMMA: writes D from C=0 (no accumulator zeroing MOVs needed).
__device__ __forceinline__ void hmma_z(float& d0, float& d1, float& d2, float& d3,
                                       const uint32_t* a, const uint32_t* b) {
    asm volatile("mma.sync.aligned.m16n8k16.row.col.f32.f16.f16.f32 "
                 "{%0,%1,%2,%3}, {%4,%5,%6,%7}, {%8,%9}, {%10,%11,%12,%13};"
                 : "=f"(d0), "=f"(d1), "=f"(d2), "=f"(d3)
                 : "r"(a[0]), "r"(a[1]), "r"(a[2]), "r"(a[3]), "r"(b[0]), "r"(b[1]),
                   "f"(0.f), "f"(0.f), "f"(0.f), "f"(0.f));
}
__device__ __forceinline__ void fold2(float& acc, float d0, float d1, uint32_t h2raw) {
    __half2 h = *reinterpret_cast<__half2*>(&h2raw);
    float2 e = __half22float2(h);
    acc = fmaf(d0, e.x, fmaf(d1, e.y, acc));
}

__device__ __forceinline__ void flush_acc(float (&acc)[8], float* raccp,
                                          int mw, int lq, int l, int col)
{
#pragma unroll
    for (int g = 0; g < 8; ++g) {
        float v = acc[g];
        v += __shfl_xor_sync(0xffffffffu, v, 1);
        v += __shfl_xor_sync(0xffffffffu, v, 2);
        if ((l & 3) == 0)
            atomicAdd(&raccp[(mw * 64 + g * 8 + lq) * 4 + col], v);
        acc[g] = 0.f;
    }
}

// A-fragments: 2 k-steps (k-eighth = 32) x 4 m-tiles = 8 ldsm4 = 32 regs.
__device__ __forceinline__ void load_afrags(uint32_t (&a)[4][2][4],
                                            uint32_t sb, int mw, int kh, int l)
{
    const uint32_t a_base = sb + OFF_A
        + (uint32_t)((mw * 64 + (l & 15)) * ROW_B + kh * 64 + (l >> 4) * 16);
#pragma unroll
    for (int mt = 0; mt < 4; ++mt)
#pragma unroll
        for (int kk = 0; kk < 2; ++kk)
            ldsm4(a[mt][kk], a_base + mt * 16 * ROW_B + kk * 32);
}

// Producer: enc (3 dims) + softmax half (broadcast centroid loads) +
// A-pack (STS.128) + partial-Z combine.
__device__ __forceinline__ void produce(
    char* smem, const float* __restrict__ X, float Mn,
    int t, int N, int pt, int q, int gp, int buf)
{
    const float4* c4 = reinterpret_cast<const float4*>(smem + OFF_CENT);
    __half2* encp = reinterpret_cast<__half2*>(smem + OFF_ENC + buf * ENC_BUF);
    float* zbuf = reinterpret_cast<float*>(smem + OFF_ZBUF);
    float* invZ = reinterpret_cast<float*>(smem + OFF_INVZ);

    const int p = t * TILE_M + pt;
    float x0 = 0.f, x1 = 0.f, x2 = 0.f;
    if (p < N) { x0 = X[p * 6 + 0]; x1 = X[p * 6 + 1]; x2 = X[p * 6 + 2]; }

#pragma unroll
    for (int dd = 0; dd < 3; ++dd) {
        const int d = q * 3 + dd;
        float xv = (p < N) ? X[p * 6 + d] : 0.f;
        float s, c;
        __sincosf(xv, &s, &c);
#pragma unroll
        for (int tt = 0; tt < 3; ++tt) {
            float s1 = 2.f * s * c;
            float c1 = fmaf(-2.f * s, s, 1.f);
            encp[(d * 6 + tt) * 136 + gp]     = __floats2half2_rn(s, s1);
            encp[(d * 6 + 3 + tt) * 136 + gp] = __floats2half2_rn(c, c1);
            s = 2.f * s1 * c1;
            c = fmaf(-2.f * s1, s1, 1.f);
        }
    }

    const float ub = sqrtf(fmaf(x0, x0, fmaf(x1, x1, x2 * x2))) * Mn;
    const float4* cb = c4 + q * 128;
    uint4* arow = reinterpret_cast<uint4*>(smem + OFF_A + pt * ROW_B + q * 256);
    float z = 0.f;
#pragma unroll 2
    for (int it = 0; it < 16; ++it) {
        uint32_t h[4];
#pragma unroll
        for (int j = 0; j < 4; ++j) {
            float4 ca = cb[it * 8 + 2 * j];
            float4 cd = cb[it * 8 + 2 * j + 1];
            float s0 = fmaf(x0, ca.x, fmaf(x1, ca.y, x2 * ca.z)) - ub;
            float s1 = fmaf(x0, cd.x, fmaf(x1, cd.y, x2 * cd.z)) - ub;
            float w0, w1;
            asm("ex2.approx.ftz.f32 %0, %1;" : "=f"(w0) : "f"(s0));
            asm("ex2.approx.ftz.f32 %0, %1;" : "=f"(w1) : "f"(s1));
            __half2 h2 = __floats2half2_rn(w0, w1);
            z += __low2float(h2) + __high2float(h2);
            h[j] = *reinterpret_cast<uint32_t*>(&h2);
        }
        arow[it] = make_uint4(h[0], h[1], h[2], h[3]);
    }
    zbuf[q * 128 + pt] = z;
    asm volatile("bar.sync 4, 256;" ::: "memory");   // producer-only barrier
    if (q == 0)
        invZ[buf * 128 + pt] = __frcp_rn(zbuf[pt] + zbuf[128 + pt]);
}

__global__ __launch_bounds__(TPB, 1)
void rgb_hmma_kernel(const float* __restrict__ X,
                     const float* __restrict__ W,
                     const float* __restrict__ cent,
                     float* __restrict__ out, int N, int n_tiles)
{
    extern __shared__ char smem[];
    const uint32_t sb = s2u(smem);
    float4* c4  = reinterpret_cast<float4*>(smem + OFF_CENT);
    float* zbuf = reinterpret_cast<float*>(smem + OFF_ZBUF);
    __half* wp  = reinterpret_cast<__half*>(smem + OFF_WP);
    float* invZ = reinterpret_cast<float*>(smem + OFF_INVZ);
    float* racc = reinterpret_cast<float*>(smem + OFF_RACC);

    const int tid = threadIdx.x;
    const int w = tid >> 5, l = tid & 31;

    for (int i = tid; i < NC; i += TPB) {
        float4 qv;
        qv.x = cent[i * 3 + 0] * LOG2E;
        qv.y = cent[i * 3 + 1] * LOG2E;
        qv.z = cent[i * 3 + 2] * LOG2E;
        qv.w = 0.f;
        c4[i] = qv;
    }
    for (int i = tid; i < 768 * EDIM; i += TPB) {
        int r = i / EDIM, e = i - r * EDIM;
        int c = r / 3, d = r - 3 * c;
        wp[(d * EDIM + e) * (ROW_B / 2) + c] = __float2half_rn(W[i]);
    }
    // zero BOTH racc buffers (1024 floats) — graph replays reuse stale smem
    for (int i = tid; i < 1024; i += TPB) racc[i] = 0.f;
    __syncthreads();

    // max centroid norm (zbuf doubles as warp-max scratch before first produce)
    float mn2 = 0.f;
    if (tid < NC) {
        float4 cc = c4[tid];
        mn2 = fmaf(cc.x, cc.x, fmaf(cc.y, cc.y, cc.z * cc.z));
    }
#pragma unroll
    for (int o = 16; o > 0; o >>= 1)
        mn2 = fmaxf(mn2, __shfl_xor_sync(0xffffffffu, mn2, o));
    if (l == 0) zbuf[w] = mn2;
    __syncthreads();
    float M2 = zbuf[0];
#pragma unroll
    for (int i = 1; i < 24; ++i) M2 = fmaxf(M2, zbuf[i]);
    const float Mn = sqrtf(M2);
    __syncthreads();   // zbuf reuse: all reads done before producers write Z

    const bool is_prod = w >= 16;
    // consumer ids (warps 0-15): 2 m-halves x 8 k-eighths, full n
    const int mw = w & 1, kh = (w >> 1) & 7, lq = l >> 2;
    // producer ids (warps 16-23): 2 threads per point (cluster halves)
    const int pp = tid - 512;
    const int pt = pp & 127, q = pp >> 7;
    const int gp = (pt >> 5) * 32 + (pt & 7) * 4 + ((pt >> 3) & 3);

    const uint32_t bl2 = sb + OFF_WP
        + (uint32_t)((l & 7) * ROW_B + ((l >> 3) & 1) * 16 + kh * 64);
    const uint32_t eb0 = sb + OFF_ENC
        + (uint32_t)((l & 3) * ENC_B + mw * 256 + lq * 16);

    const int G = gridDim.x;
    const int bid = blockIdx.x;
    const int nw = (bid < n_tiles) ? ((n_tiles - 1 - bid) / G + 1) : 0;

    if (is_prod && bid < n_tiles)
        produce(smem, X, Mn, bid, N, pt, q, gp, 0);
    __syncthreads();

    uint32_t a[4][2][4];
    int i = 0;
    for (int t = bid; t < n_tiles; t += G, ++i) {
        const int buf = i & 1;
        if (!is_prod) {
            load_afrags(a, sb, mw, kh, l);
            asm volatile("bar.arrive 3, 768;" ::: "memory");

            const uint32_t eb = eb0 + (uint32_t)buf * ENC_BUF;
            float* raccp = racc + buf * 512;
            float acc[8];
#pragma unroll
            for (int g = 0; g < 8; ++g) acc[g] = 0.f;

#pragma unroll
            for (int dch = 0; dch < 3; ++dch) {
#pragma unroll
                for (int ss = 0; ss < 9; ++ss) {
                    const uint32_t bs = bl2 + (uint32_t)((dch * 9 + ss) * 8 * ROW_B);
                    uint32_t b0[2], b1[2];
                    ldsm2(b0, bs);
                    ldsm2(b1, bs + 32);
                    const uint32_t ea = eb + (uint32_t)(ss * 4) * ENC_B;
                    uint32_t e0, e1, e2, e3;
                    float d[8];
                    // m-tile pair 0 (warp rows 0..31)
                    hmma_z(d[0], d[1], d[2], d[3], a[0][0], b0);
                    hmma_z(d[4], d[5], d[6], d[7], a[1][0], b0);
                    hmma(d[0], d[1], d[2], d[3], a[0][1], b1);
                    hmma(d[4], d[5], d[6], d[7], a[1][1], b1);
                    lds128(e0, e1, e2, e3, ea);
                    fold2(acc[0], d[0], d[1], e0);
                    fold2(acc[1], d[2], d[3], e1);
                    fold2(acc[2], d[4], d[5], e2);
                    fold2(acc[3], d[6], d[7], e3);
                    // m-tile pair 1 (warp rows 32..63)
                    hmma_z(d[0], d[1], d[2], d[3], a[2][0], b0);
                    hmma_z(d[4], d[5], d[6], d[7], a[3][0], b0);
                    hmma(d[0], d[1], d[2], d[3], a[2][1], b1);
                    hmma(d[4], d[5], d[6], d[7], a[3][1], b1);
                    lds128(e0, e1, e2, e3, ea + 128);
                    fold2(acc[4], d[0], d[1], e0);
                    fold2(acc[5], d[2], d[3], e1);
                    fold2(acc[6], d[4], d[5], e2);
                    fold2(acc[7], d[6], d[7], e3);
                }
                flush_acc(acc, raccp, mw, lq, l, dch);
            }
        } else {
            if (i > 0 && q == 0) {
                float* rp = racc + (buf ^ 1) * 512 + pt * 4;
                const int po = (t - G) * TILE_M + pt;
                if (po < N) {
                    const float iz = invZ[(buf ^ 1) * 128 + pt];
                    out[po * 3 + 0] = rp[0] * iz;
                    out[po * 3 + 1] = rp[1] * iz;
                    out[po * 3 + 2] = rp[2] * iz;
                }
                rp[0] = 0.f; rp[1] = 0.f; rp[2] = 0.f; rp[3] = 0.f;
            }
            asm volatile("bar.sync 3, 768;" ::: "memory");
            if (t + G < n_tiles)
                produce(smem, X, Mn, t + G, N, pt, q, gp, buf ^ 1);
        }
        __syncthreads();
    }

    if (is_prod && q == 0 && nw > 0) {
        const int bufl = (nw - 1) & 1;
        const int tl = bid + (nw - 1) * G;
        const int po = tl * TILE_M + pt;
        if (po < N) {
            const float iz = invZ[bufl * 128 + pt];
            float* rp = racc + bufl * 512 + pt * 4;
            out[po * 3 + 0] = rp[0] * iz;
            out[po * 3 + 1] = rp[1] * iz;
            out[po * 3 + 2] = rp[2] * iz;
        }
    }
}

extern "C" void kernel_launch(void* const* d_in, const int* in_sizes, int n_in,
                              void* d_out, int out_size)
{
    const float* X    = (const float*)d_in[0];  // [N, 6]
    const float* W    = (const float*)d_in[1];  // [768, 72]
    const float* cent = (const float*)d_in[2];  // [256, 3]
    float* out = (float*)d_out;                 // [N, 3]

    const int N = in_sizes[0] / 6;
    const int n_tiles = (N + TILE_M - 1) / TILE_M;

    int dev = 0, sms = 148;
    cudaGetDevice(&dev);
    cudaDeviceGetAttribute(&sms, cudaDevAttrMultiProcessorCount, dev);

    cudaFuncSetAttribute(rgb_hmma_kernel,
                         cudaFuncAttributeMaxDynamicSharedMemorySize, SMEM_BYTES);

    const int grid = n_tiles < sms ? n_tiles : sms;
    rgb_hmma_kernel<<<grid, TPB, SMEM_BYTES>>>(X, W, cent, out, N, n_tiles);
}